// round 1
// baseline (speedup 1.0000x reference)
#include <cuda_runtime.h>
#include <math.h>

#define BS   8
#define RES  128
#define NQ   (RES*RES)       // 16384
#define CCH  128
#define NH   8
#define NP   4
#define HDQ  16
#define NTOT (BS*NQ)         // 131072

// scratch (device globals; no allocation)
__device__ float g_value[(size_t)NTOT*CCH];    // (b,n, h*hd+d)
__device__ float g_off  [(size_t)NTOT*NH*NP*2];
__device__ float g_attn [(size_t)NTOT*NH*NP];
__device__ float g_sampled[(size_t)NTOT*CCH];

// ---------------------------------------------------------------------------
// Kernel 1: fused projection  query @ [Wv | Woff | Wattn]  (+bias, +softmax)
// Tile: 64 queries x 224 cols, 256 threads, per-thread 8x7 register tile.
// ---------------------------------------------------------------------------
__global__ __launch_bounds__(256) void proj_kernel(
    const float* __restrict__ query,
    const float* __restrict__ Wv,   const float* __restrict__ bv,
    const float* __restrict__ Woff, const float* __restrict__ boff,
    const float* __restrict__ Wattn,const float* __restrict__ battn)
{
    __shared__ float Qs[64*128];     // 32 KB
    __shared__ float Ws[16*224];     // 14 KB (reused for softmax staging)

    const int tid = threadIdx.x;
    const size_t q0 = (size_t)blockIdx.x * 64;

    // load 64x128 query tile (vectorized)
    {
        const float4* src = (const float4*)(query + q0*CCH);
        float4* dst = (float4*)Qs;
        #pragma unroll
        for (int t = 0; t < 8; t++) dst[tid + 256*t] = src[tid + 256*t];
    }

    const int tx = tid & 31;   // col lane: cols tx + 32*j
    const int ty = tid >> 5;   // query group: rows ty*8 .. ty*8+7

    float acc[8][7];
    #pragma unroll
    for (int i = 0; i < 8; i++)
        #pragma unroll
        for (int j = 0; j < 7; j++) acc[i][j] = 0.f;

    for (int kc = 0; kc < 8; kc++) {
        __syncthreads();
        // load W chunk rows [kc*16, kc*16+16), 224 fused cols
        #pragma unroll
        for (int t = 0; t < 14; t++) {
            int idx = tid + 256*t;
            int r = idx / 224, c = idx - r*224;
            int k = kc*16 + r;
            float w;
            if (c < 128)      w = Wv  [k*128 + c];
            else if (c < 192) w = Woff[k*64  + (c-128)];
            else              w = Wattn[k*32 + (c-192)];
            Ws[r*224 + c] = w;
        }
        __syncthreads();
        #pragma unroll
        for (int kk = 0; kk < 16; kk++) {
            float wv[7];
            #pragma unroll
            for (int j = 0; j < 7; j++) wv[j] = Ws[kk*224 + tx + 32*j];
            #pragma unroll
            for (int i = 0; i < 8; i++) {
                float qv = Qs[(ty*8+i)*128 + kc*16 + kk];
                #pragma unroll
                for (int j = 0; j < 7; j++) acc[i][j] = fmaf(qv, wv[j], acc[i][j]);
            }
        }
    }
    __syncthreads();  // before reusing Ws as softmax staging

    // epilogue: value + off writes; attn logits -> shared
    float bvv[4];
    #pragma unroll
    for (int j = 0; j < 4; j++) bvv[j] = bv[tx + 32*j];
    float bo0 = boff[tx], bo1 = boff[tx + 32];
    float ba  = battn[tx];

    #pragma unroll
    for (int i = 0; i < 8; i++) {
        size_t n = q0 + ty*8 + i;
        #pragma unroll
        for (int j = 0; j < 4; j++)
            g_value[n*CCH + tx + 32*j] = acc[i][j] + bvv[j];
        g_off[n*64 + tx]      = acc[i][4] + bo0;
        g_off[n*64 + tx + 32] = acc[i][5] + bo1;
        Ws[(ty*8+i)*32 + tx]  = acc[i][6] + ba;   // attn logit, col tx = h*4+p
    }
    __syncthreads();

    // softmax over P=4 for each of 64*8 (query, head) groups
    for (int g = tid; g < 64*NH; g += 256) {
        int ql = g >> 3, h = g & 7;
        float l0 = Ws[ql*32 + h*4 + 0];
        float l1 = Ws[ql*32 + h*4 + 1];
        float l2 = Ws[ql*32 + h*4 + 2];
        float l3 = Ws[ql*32 + h*4 + 3];
        float m = fmaxf(fmaxf(l0,l1), fmaxf(l2,l3));
        float e0 = __expf(l0-m), e1 = __expf(l1-m), e2 = __expf(l2-m), e3 = __expf(l3-m);
        float inv = 1.f / (e0+e1+e2+e3);
        size_t n = q0 + ql;
        g_attn[n*32 + h*4 + 0] = e0*inv;
        g_attn[n*32 + h*4 + 1] = e1*inv;
        g_attn[n*32 + h*4 + 2] = e2*inv;
        g_attn[n*32 + h*4 + 3] = e3*inv;
    }
}

// ---------------------------------------------------------------------------
// Kernel 2: bilinear sampling + attention-weighted sum over P.
// One warp per query; lane = h*4 + dq (dq selects a float4 of 4 channels).
// ---------------------------------------------------------------------------
__global__ __launch_bounds__(128) void sample_kernel()
{
    const int lane = threadIdx.x & 31;
    const int qloc = threadIdx.x >> 5;
    const size_t n = (size_t)blockIdx.x * 4 + qloc;   // 0..131071
    const int b = (int)(n >> 14);
    const int q = (int)(n & (NQ-1));
    const int h  = lane >> 2;
    const int dq = lane & 3;

    const float refx = (float)(q & 127) * (1.0f/127.0f);
    const float refy = (float)(q >> 7)  * (1.0f/127.0f);

    const float* off  = g_off  + n*64 + h*8;
    const float* attn = g_attn + n*32 + h*4;
    const float* vb   = g_value + ((size_t)b*NQ)*CCH + h*HDQ + dq*4;

    float4 acc = make_float4(0.f,0.f,0.f,0.f);

    #pragma unroll
    for (int p = 0; p < NP; p++) {
        float ox = off[p*2 + 0];
        float oy = off[p*2 + 1];
        float a  = attn[p];
        // matches ref: x = (refx + ox/128)*128 - 0.5  (div/mul by 128 exact)
        float x = (refx + ox*(1.0f/128.0f))*128.0f - 0.5f;
        float y = (refy + oy*(1.0f/128.0f))*128.0f - 0.5f;
        float x0f = floorf(x), y0f = floorf(y);
        int x0 = (int)x0f, y0 = (int)y0f;
        float wx = x - x0f, wy = y - y0f;
        float w00 = (1.f-wx)*(1.f-wy)*a;
        float w10 = wx*(1.f-wy)*a;
        float w01 = (1.f-wx)*wy*a;
        float w11 = wx*wy*a;

        bool xv0 = (unsigned)x0     < 128u;
        bool xv1 = (unsigned)(x0+1) < 128u;
        bool yv0 = (unsigned)y0     < 128u;
        bool yv1 = (unsigned)(y0+1) < 128u;

        if (yv0) {
            const float* rp = vb + (size_t)(y0*128)*CCH;
            if (xv0) { float4 v = *(const float4*)(rp + (size_t)x0*CCH);
                       acc.x += w00*v.x; acc.y += w00*v.y; acc.z += w00*v.z; acc.w += w00*v.w; }
            if (xv1) { float4 v = *(const float4*)(rp + (size_t)(x0+1)*CCH);
                       acc.x += w10*v.x; acc.y += w10*v.y; acc.z += w10*v.z; acc.w += w10*v.w; }
        }
        if (yv1) {
            const float* rp = vb + (size_t)((y0+1)*128)*CCH;
            if (xv0) { float4 v = *(const float4*)(rp + (size_t)x0*CCH);
                       acc.x += w01*v.x; acc.y += w01*v.y; acc.z += w01*v.z; acc.w += w01*v.w; }
            if (xv1) { float4 v = *(const float4*)(rp + (size_t)(x0+1)*CCH);
                       acc.x += w11*v.x; acc.y += w11*v.y; acc.z += w11*v.z; acc.w += w11*v.w; }
        }
    }

    *(float4*)(g_sampled + n*CCH + h*HDQ + dq*4) = acc;
}

// ---------------------------------------------------------------------------
// Kernel 3: out = sampled @ Wout + bout + 2*query
// Tile: 64 queries x 128 cols, 256 threads, per-thread 8x4 register tile.
// ---------------------------------------------------------------------------
__global__ __launch_bounds__(256) void out_kernel(
    const float* __restrict__ Wout, const float* __restrict__ bout,
    const float* __restrict__ query, float* __restrict__ out)
{
    __shared__ float Ss[64*128];   // 32 KB
    __shared__ float Ws[16*128];   // 8 KB

    const int tid = threadIdx.x;
    const size_t q0 = (size_t)blockIdx.x * 64;

    {
        const float4* src = (const float4*)(g_sampled + q0*CCH);
        float4* dst = (float4*)Ss;
        #pragma unroll
        for (int t = 0; t < 8; t++) dst[tid + 256*t] = src[tid + 256*t];
    }

    const int tx = tid & 31;
    const int ty = tid >> 5;

    float acc[8][4];
    #pragma unroll
    for (int i = 0; i < 8; i++)
        #pragma unroll
        for (int j = 0; j < 4; j++) acc[i][j] = 0.f;

    for (int kc = 0; kc < 8; kc++) {
        __syncthreads();
        #pragma unroll
        for (int t = 0; t < 8; t++) {
            int idx = tid + 256*t;
            int r = idx >> 7, c = idx & 127;
            Ws[idx] = Wout[(kc*16 + r)*128 + c];
        }
        __syncthreads();
        #pragma unroll
        for (int kk = 0; kk < 16; kk++) {
            float wv[4];
            #pragma unroll
            for (int j = 0; j < 4; j++) wv[j] = Ws[kk*128 + tx + 32*j];
            #pragma unroll
            for (int i = 0; i < 8; i++) {
                float sv = Ss[(ty*8+i)*128 + kc*16 + kk];
                #pragma unroll
                for (int j = 0; j < 4; j++) acc[i][j] = fmaf(sv, wv[j], acc[i][j]);
            }
        }
    }

    float bo[4];
    #pragma unroll
    for (int j = 0; j < 4; j++) bo[j] = bout[tx + 32*j];

    #pragma unroll
    for (int i = 0; i < 8; i++) {
        size_t n = q0 + ty*8 + i;
        #pragma unroll
        for (int j = 0; j < 4; j++) {
            int c = tx + 32*j;
            out[n*CCH + c] = acc[i][j] + bo[j] + 2.0f*query[n*CCH + c];
        }
    }
}

// ---------------------------------------------------------------------------
extern "C" void kernel_launch(void* const* d_in, const int* in_sizes, int n_in,
                              void* d_out, int out_size)
{
    const float* query = (const float*)d_in[0];
    const float* Wv    = (const float*)d_in[1];
    const float* bv    = (const float*)d_in[2];
    const float* Woff  = (const float*)d_in[3];
    const float* boff  = (const float*)d_in[4];
    const float* Wattn = (const float*)d_in[5];
    const float* battn = (const float*)d_in[6];
    const float* Wout  = (const float*)d_in[7];
    const float* bout  = (const float*)d_in[8];
    float* out = (float*)d_out;

    proj_kernel<<<NTOT/64, 256>>>(query, Wv, bv, Woff, boff, Wattn, battn);
    sample_kernel<<<NTOT/4, 128>>>();
    out_kernel<<<NTOT/64, 256>>>(Wout, bout, query, out);
}

// round 8
// speedup vs baseline: 2.5960x; 2.5960x over previous
#include <cuda_runtime.h>
#include <cuda_bf16.h>
#include <stdint.h>
#include <math.h>

#define BS   8
#define RES  128
#define NQ   (RES*RES)       // 16384
#define CCH  128
#define NH   8
#define NP   4
#define NTOT (BS*NQ)         // 131072

// ---------------- scratch (device globals; no allocation) -------------------
__device__ float g_value  [(size_t)NTOT*CCH];
__device__ float g_off    [(size_t)NTOT*64];
__device__ float g_attn   [(size_t)NTOT*32];
__device__ float g_sampled[(size_t)NTOT*CCH];

// packed transposed bf16 weight images, [n][k] row-major, k contiguous
__device__ __align__(16) __nv_bfloat16 g_w1_hi[128*128];  // Wv^T
__device__ __align__(16) __nv_bfloat16 g_w1_lo[128*128];
__device__ __align__(16) __nv_bfloat16 g_w2_hi[96*128];   // [Woff|Wattn]^T
__device__ __align__(16) __nv_bfloat16 g_w3_hi[128*128];  // Wout^T
__device__ __align__(16) __nv_bfloat16 g_w3_lo[128*128];

// ---------------- helpers ---------------------------------------------------
__device__ __forceinline__ uint32_t packbf(float a, float b) {
    uint32_t r;
    asm("cvt.rn.bf16x2.f32 %0, %1, %2;" : "=r"(r) : "f"(b), "f"(a));
    return r;
}
// split float4 (4 consecutive k) into hi/lo bf16x2 pairs
__device__ __forceinline__ void split4(float4 v, uint2& hi, uint2& lo) {
    uint32_t h01 = packbf(v.x, v.y);
    uint32_t h23 = packbf(v.z, v.w);
    float f0 = __uint_as_float(h01 << 16);
    float f1 = __uint_as_float(h01 & 0xffff0000u);
    float f2 = __uint_as_float(h23 << 16);
    float f3 = __uint_as_float(h23 & 0xffff0000u);
    hi = make_uint2(h01, h23);
    lo = make_uint2(packbf(v.x - f0, v.y - f1), packbf(v.z - f2, v.w - f3));
}

// mma.sync m16n8k16 row.col bf16 -> f32 accumulate (in-place)
__device__ __forceinline__ void mma16816(float* c, const uint32_t* a, const uint32_t* b) {
    asm volatile(
        "mma.sync.aligned.m16n8k16.row.col.f32.bf16.bf16.f32 "
        "{%0,%1,%2,%3}, {%4,%5,%6,%7}, {%8,%9}, {%0,%1,%2,%3};"
        : "+f"(c[0]), "+f"(c[1]), "+f"(c[2]), "+f"(c[3])
        : "r"(a[0]), "r"(a[1]), "r"(a[2]), "r"(a[3]), "r"(b[0]), "r"(b[1]));
}

#define PSTR 136   // padded bf16 row stride in smem (conflict-free fragment LDS)

// ---------------------------------------------------------------------------
// prep: transposed, split-bf16 packed weight images
// ---------------------------------------------------------------------------
__global__ void prep_kernel(const float* __restrict__ Wv, const float* __restrict__ Woff,
                            const float* __restrict__ Wattn, const float* __restrict__ Wout)
{
    int i = blockIdx.x * 256 + threadIdx.x;
    if (i < 16384) {
        int k = i >> 7, n = i & 127;
        int o = n * 128 + k;
        {
            float v = Wv[i];
            __nv_bfloat16 h = __float2bfloat16(v);
            g_w1_hi[o] = h;
            g_w1_lo[o] = __float2bfloat16(v - __bfloat162float(h));
        }
        {
            float v = Wout[i];
            __nv_bfloat16 h = __float2bfloat16(v);
            g_w3_hi[o] = h;
            g_w3_lo[o] = __float2bfloat16(v - __bfloat162float(h));
        }
    } else if (i < 16384 + 12288) {
        int j = i - 16384;
        int k = j / 96, n = j - 96 * k;
        float v = (n < 64) ? Woff[k * 64 + n] : Wattn[k * 32 + (n - 64)];
        g_w2_hi[n * 128 + k] = __float2bfloat16(v);
    }
}

// ---------------------------------------------------------------------------
// Kernel 1: proj. CTA tile 128 rows x 224 cols, K=128. 8 warps = 4(M) x 2(N).
// cols 0..127 -> value (3-term), 128..191 -> off (1-term), 192..223 -> attn.
// ---------------------------------------------------------------------------
#define P_AH   0u
#define P_AL   (P_AH + 128u*PSTR*2u)
#define P_WVH  (P_AL + 128u*PSTR*2u)
#define P_WVL  (P_WVH + 128u*PSTR*2u)
#define P_W2   (P_WVL + 128u*PSTR*2u)
#define PROJ_SMEM (P_W2 + 96u*PSTR*2u)     // 165376

__global__ __launch_bounds__(256, 1) void proj_kernel(
    const float* __restrict__ query,
    const float* __restrict__ bv, const float* __restrict__ boff,
    const float* __restrict__ battn)
{
    extern __shared__ __align__(16) unsigned char smem[];
    const int tid = threadIdx.x;
    const size_t q0 = (size_t)blockIdx.x * 128;

    // ---- stage A: 128x128 fp32 -> hi/lo bf16, padded rows (4096 float4) ----
    {
        const float4* qsrc = (const float4*)(query + q0 * CCH);
        #pragma unroll
        for (int it = 0; it < 16; it++) {
            int idx4 = it * 256 + tid;
            float4 v = qsrc[idx4];
            int row = idx4 >> 5, k0 = (idx4 & 31) << 2;
            uint2 hi, lo; split4(v, hi, lo);
            *(uint2*)(smem + P_AH + row * (PSTR*2) + k0 * 2) = hi;
            *(uint2*)(smem + P_AL + row * (PSTR*2) + k0 * 2) = lo;
        }
    }
    // ---- stage B: copy packed images into padded rows ----
    {
        const uint4* s;
        s = (const uint4*)g_w1_hi;
        #pragma unroll
        for (int it = 0; it < 8; it++) {
            int idx = it * 256 + tid; int row = idx >> 4, seg = idx & 15;
            *(uint4*)(smem + P_WVH + row * (PSTR*2) + seg * 16) = s[idx];
        }
        s = (const uint4*)g_w1_lo;
        #pragma unroll
        for (int it = 0; it < 8; it++) {
            int idx = it * 256 + tid; int row = idx >> 4, seg = idx & 15;
            *(uint4*)(smem + P_WVL + row * (PSTR*2) + seg * 16) = s[idx];
        }
        s = (const uint4*)g_w2_hi;
        #pragma unroll
        for (int it = 0; it < 6; it++) {
            int idx = it * 256 + tid; int row = idx >> 4, seg = idx & 15;
            *(uint4*)(smem + P_W2 + row * (PSTR*2) + seg * 16) = s[idx];
        }
    }
    __syncthreads();

    const int lane = tid & 31, wid = tid >> 5;
    const int wm = wid & 3, wn = wid >> 2;
    const int gr = lane >> 2, tg = lane & 3;

    const uint32_t* Ah  = (const uint32_t*)(smem + P_AH);
    const uint32_t* Al  = (const uint32_t*)(smem + P_AL);
    const uint32_t* Bvh = (const uint32_t*)(smem + P_WVH);
    const uint32_t* Bvl = (const uint32_t*)(smem + P_WVL);
    const uint32_t* B2  = (const uint32_t*)(smem + P_W2);

    float accV[8][2][4];
    float accE[6][2][4];
    #pragma unroll
    for (int j = 0; j < 8; j++)
        #pragma unroll
        for (int mt = 0; mt < 2; mt++)
            #pragma unroll
            for (int e = 0; e < 4; e++) accV[j][mt][e] = 0.f;
    #pragma unroll
    for (int j = 0; j < 6; j++)
        #pragma unroll
        for (int mt = 0; mt < 2; mt++)
            #pragma unroll
            for (int e = 0; e < 4; e++) accE[j][mt][e] = 0.f;

    const int r0 = wm * 32 + gr;
    const int kb = tg * 2;

    #pragma unroll
    for (int kc = 0; kc < 8; kc++) {
        const int k0 = kc * 16 + kb;
        const int kw0 = k0 >> 1, kw1 = (k0 + 8) >> 1;
        uint32_t ah[2][4], al[2][4];
        #pragma unroll
        for (int mt = 0; mt < 2; mt++) {
            int r = r0 + mt * 16;
            ah[mt][0] = Ah[r * 68 + kw0];
            ah[mt][1] = Ah[(r + 8) * 68 + kw0];
            ah[mt][2] = Ah[r * 68 + kw1];
            ah[mt][3] = Ah[(r + 8) * 68 + kw1];
            al[mt][0] = Al[r * 68 + kw0];
            al[mt][1] = Al[(r + 8) * 68 + kw0];
            al[mt][2] = Al[r * 68 + kw1];
            al[mt][3] = Al[(r + 8) * 68 + kw1];
        }
        #pragma unroll
        for (int j = 0; j < 8; j++) {
            int n = wn * 64 + j * 8 + gr;
            uint32_t bh[2] = { Bvh[n * 68 + kw0], Bvh[n * 68 + kw1] };
            uint32_t bl[2] = { Bvl[n * 68 + kw0], Bvl[n * 68 + kw1] };
            #pragma unroll
            for (int mt = 0; mt < 2; mt++) {
                mma16816(accV[j][mt], ah[mt], bh);
                mma16816(accV[j][mt], ah[mt], bl);
                mma16816(accV[j][mt], al[mt], bh);
            }
        }
        #pragma unroll
        for (int j = 0; j < 6; j++) {
            int n = wn * 48 + j * 8 + gr;
            uint32_t b2[2] = { B2[n * 68 + kw0], B2[n * 68 + kw1] };
            #pragma unroll
            for (int mt = 0; mt < 2; mt++) mma16816(accE[j][mt], ah[mt], b2);
        }
    }

    __syncthreads();   // all warps done reading smem before attn staging reuse

    // ---- epilogue ----
    const int c0 = tg * 2;
    // value cols
    #pragma unroll
    for (int j = 0; j < 8; j++) {
        int c = wn * 64 + j * 8 + c0;
        float2 b = *(const float2*)(bv + c);
        #pragma unroll
        for (int mt = 0; mt < 2; mt++) {
            #pragma unroll
            for (int hr = 0; hr < 2; hr++) {
                int r = wm * 32 + mt * 16 + gr + hr * 8;
                float2 o = make_float2(accV[j][mt][hr * 2 + 0] + b.x,
                                       accV[j][mt][hr * 2 + 1] + b.y);
                *(float2*)(g_value + (q0 + r) * CCH + c) = o;
            }
        }
    }
    // extra cols (off / attn)
    float* Lst = (float*)(smem + P_AH);   // attn logit staging: [128][32]
    #pragma unroll
    for (int j = 0; j < 6; j++) {
        int ce = 128 + wn * 48 + j * 8 + c0;
        if (ce < 192) {
            float2 b = *(const float2*)(boff + (ce - 128));
            #pragma unroll
            for (int mt = 0; mt < 2; mt++)
                #pragma unroll
                for (int hr = 0; hr < 2; hr++) {
                    int r = wm * 32 + mt * 16 + gr + hr * 8;
                    float2 o = make_float2(accE[j][mt][hr * 2 + 0] + b.x,
                                           accE[j][mt][hr * 2 + 1] + b.y);
                    *(float2*)(g_off + (q0 + r) * 64 + (ce - 128)) = o;
                }
        } else {
            int ca = ce - 192;
            float b0 = battn[ca], b1 = battn[ca + 1];
            #pragma unroll
            for (int mt = 0; mt < 2; mt++)
                #pragma unroll
                for (int hr = 0; hr < 2; hr++) {
                    int r = wm * 32 + mt * 16 + gr + hr * 8;
                    Lst[r * 32 + ca]     = accE[j][mt][hr * 2 + 0] + b0;
                    Lst[r * 32 + ca + 1] = accE[j][mt][hr * 2 + 1] + b1;
                }
        }
    }
    __syncthreads();

    // softmax over P=4 for 128*8 groups
    #pragma unroll
    for (int g = tid; g < 1024; g += 256) {
        int row = g >> 3, h = g & 7;
        float4 l = *(const float4*)(Lst + row * 32 + h * 4);
        float m = fmaxf(fmaxf(l.x, l.y), fmaxf(l.z, l.w));
        float e0 = __expf(l.x - m), e1 = __expf(l.y - m),
              e2 = __expf(l.z - m), e3 = __expf(l.w - m);
        float inv = 1.f / (e0 + e1 + e2 + e3);
        *(float4*)(g_attn + (q0 + row) * 32 + h * 4) =
            make_float4(e0 * inv, e1 * inv, e2 * inv, e3 * inv);
    }
}

// ---------------------------------------------------------------------------
// Kernel 2: bilinear sampling + attention-weighted sum
// ---------------------------------------------------------------------------
__global__ __launch_bounds__(128) void sample_kernel()
{
    const int lane = threadIdx.x & 31;
    const int qloc = threadIdx.x >> 5;
    const size_t n = (size_t)blockIdx.x * 4 + qloc;
    const int b = (int)(n >> 14);
    const int q = (int)(n & (NQ - 1));
    const int h  = lane >> 2;
    const int dq = lane & 3;

    const float refx = (float)(q & 127) * (1.0f / 127.0f);
    const float refy = (float)(q >> 7)  * (1.0f / 127.0f);

    const float* off  = g_off  + n * 64 + h * 8;
    const float* attn = g_attn + n * 32 + h * 4;
    const float* vb   = g_value + ((size_t)b * NQ) * CCH + h * 16 + dq * 4;

    float4 acc = make_float4(0.f, 0.f, 0.f, 0.f);

    #pragma unroll
    for (int p = 0; p < NP; p++) {
        float ox = off[p * 2 + 0];
        float oy = off[p * 2 + 1];
        float a  = attn[p];
        float x = (refx + ox * (1.0f / 128.0f)) * 128.0f - 0.5f;
        float y = (refy + oy * (1.0f / 128.0f)) * 128.0f - 0.5f;
        float x0f = floorf(x), y0f = floorf(y);
        int x0 = (int)x0f, y0 = (int)y0f;
        float wx = x - x0f, wy = y - y0f;
        float w00 = (1.f - wx) * (1.f - wy) * a;
        float w10 = wx * (1.f - wy) * a;
        float w01 = (1.f - wx) * wy * a;
        float w11 = wx * wy * a;

        bool xv0 = (unsigned)x0       < 128u;
        bool xv1 = (unsigned)(x0 + 1) < 128u;
        bool yv0 = (unsigned)y0       < 128u;
        bool yv1 = (unsigned)(y0 + 1) < 128u;

        if (yv0) {
            const float* rp = vb + (size_t)(y0 * 128) * CCH;
            if (xv0) { float4 v = *(const float4*)(rp + (size_t)x0 * CCH);
                       acc.x += w00 * v.x; acc.y += w00 * v.y; acc.z += w00 * v.z; acc.w += w00 * v.w; }
            if (xv1) { float4 v = *(const float4*)(rp + (size_t)(x0 + 1) * CCH);
                       acc.x += w10 * v.x; acc.y += w10 * v.y; acc.z += w10 * v.z; acc.w += w10 * v.w; }
        }
        if (yv1) {
            const float* rp = vb + (size_t)((y0 + 1) * 128) * CCH;
            if (xv0) { float4 v = *(const float4*)(rp + (size_t)x0 * CCH);
                       acc.x += w01 * v.x; acc.y += w01 * v.y; acc.z += w01 * v.z; acc.w += w01 * v.w; }
            if (xv1) { float4 v = *(const float4*)(rp + (size_t)(x0 + 1) * CCH);
                       acc.x += w11 * v.x; acc.y += w11 * v.y; acc.z += w11 * v.z; acc.w += w11 * v.w; }
        }
    }

    *(float4*)(g_sampled + n * CCH + h * 16 + dq * 4) = acc;
}

// ---------------------------------------------------------------------------
// Kernel 3: out = sampled @ Wout + bout + 2*query. 3-term bf16 mma.
// ---------------------------------------------------------------------------
#define O_AH   0u
#define O_AL   (O_AH + 128u*PSTR*2u)
#define O_WH   (O_AL + 128u*PSTR*2u)
#define O_WL   (O_WH + 128u*PSTR*2u)
#define OUT_SMEM (O_WL + 128u*PSTR*2u)   // 139264

__global__ __launch_bounds__(256, 1) void out_kernel(
    const float* __restrict__ bout, const float* __restrict__ query,
    float* __restrict__ out)
{
    extern __shared__ __align__(16) unsigned char smem[];
    const int tid = threadIdx.x;
    const size_t q0 = (size_t)blockIdx.x * 128;

    {
        const float4* asrc = (const float4*)(g_sampled + q0 * CCH);
        #pragma unroll
        for (int it = 0; it < 16; it++) {
            int idx4 = it * 256 + tid;
            float4 v = asrc[idx4];
            int row = idx4 >> 5, k0 = (idx4 & 31) << 2;
            uint2 hi, lo; split4(v, hi, lo);
            *(uint2*)(smem + O_AH + row * (PSTR*2) + k0 * 2) = hi;
            *(uint2*)(smem + O_AL + row * (PSTR*2) + k0 * 2) = lo;
        }
        const uint4* s;
        s = (const uint4*)g_w3_hi;
        #pragma unroll
        for (int it = 0; it < 8; it++) {
            int idx = it * 256 + tid; int row = idx >> 4, seg = idx & 15;
            *(uint4*)(smem + O_WH + row * (PSTR*2) + seg * 16) = s[idx];
        }
        s = (const uint4*)g_w3_lo;
        #pragma unroll
        for (int it = 0; it < 8; it++) {
            int idx = it * 256 + tid; int row = idx >> 4, seg = idx & 15;
            *(uint4*)(smem + O_WL + row * (PSTR*2) + seg * 16) = s[idx];
        }
    }
    __syncthreads();

    const int lane = tid & 31, wid = tid >> 5;
    const int wm = wid & 3, wn = wid >> 2;
    const int gr = lane >> 2, tg = lane & 3;

    const uint32_t* Ah = (const uint32_t*)(smem + O_AH);
    const uint32_t* Al = (const uint32_t*)(smem + O_AL);
    const uint32_t* Bh = (const uint32_t*)(smem + O_WH);
    const uint32_t* Bl = (const uint32_t*)(smem + O_WL);

    float acc[8][2][4];
    #pragma unroll
    for (int j = 0; j < 8; j++)
        #pragma unroll
        for (int mt = 0; mt < 2; mt++)
            #pragma unroll
            for (int e = 0; e < 4; e++) acc[j][mt][e] = 0.f;

    const int r0 = wm * 32 + gr;
    const int kb = tg * 2;

    #pragma unroll
    for (int kc = 0; kc < 8; kc++) {
        const int k0 = kc * 16 + kb;
        const int kw0 = k0 >> 1, kw1 = (k0 + 8) >> 1;
        uint32_t ah[2][4], al[2][4];
        #pragma unroll
        for (int mt = 0; mt < 2; mt++) {
            int r = r0 + mt * 16;
            ah[mt][0] = Ah[r * 68 + kw0];
            ah[mt][1] = Ah[(r + 8) * 68 + kw0];
            ah[mt][2] = Ah[r * 68 + kw1];
            ah[mt][3] = Ah[(r + 8) * 68 + kw1];
            al[mt][0] = Al[r * 68 + kw0];
            al[mt][1] = Al[(r + 8) * 68 + kw0];
            al[mt][2] = Al[r * 68 + kw1];
            al[mt][3] = Al[(r + 8) * 68 + kw1];
        }
        #pragma unroll
        for (int j = 0; j < 8; j++) {
            int n = wn * 64 + j * 8 + gr;
            uint32_t bh[2] = { Bh[n * 68 + kw0], Bh[n * 68 + kw1] };
            uint32_t bl[2] = { Bl[n * 68 + kw0], Bl[n * 68 + kw1] };
            #pragma unroll
            for (int mt = 0; mt < 2; mt++) {
                mma16816(acc[j][mt], ah[mt], bh);
                mma16816(acc[j][mt], ah[mt], bl);
                mma16816(acc[j][mt], al[mt], bh);
            }
        }
    }

    const int c0 = tg * 2;
    #pragma unroll
    for (int j = 0; j < 8; j++) {
        int c = wn * 64 + j * 8 + c0;
        float2 b = *(const float2*)(bout + c);
        #pragma unroll
        for (int mt = 0; mt < 2; mt++) {
            #pragma unroll
            for (int hr = 0; hr < 2; hr++) {
                int r = wm * 32 + mt * 16 + gr + hr * 8;
                size_t nn = q0 + r;
                float2 qv = *(const float2*)(query + nn * CCH + c);
                float2 o = make_float2(acc[j][mt][hr * 2 + 0] + b.x + 2.0f * qv.x,
                                       acc[j][mt][hr * 2 + 1] + b.y + 2.0f * qv.y);
                *(float2*)(out + nn * CCH + c) = o;
            }
        }
    }
}

// ---------------------------------------------------------------------------
extern "C" void kernel_launch(void* const* d_in, const int* in_sizes, int n_in,
                              void* d_out, int out_size)
{
    const float* query = (const float*)d_in[0];
    const float* Wv    = (const float*)d_in[1];
    const float* bv    = (const float*)d_in[2];
    const float* Woff  = (const float*)d_in[3];
    const float* boff  = (const float*)d_in[4];
    const float* Wattn = (const float*)d_in[5];
    const float* battn = (const float*)d_in[6];
    const float* Wout  = (const float*)d_in[7];
    const float* bout  = (const float*)d_in[8];
    float* out = (float*)d_out;

    cudaFuncSetAttribute(proj_kernel, cudaFuncAttributeMaxDynamicSharedMemorySize, PROJ_SMEM);
    cudaFuncSetAttribute(out_kernel,  cudaFuncAttributeMaxDynamicSharedMemorySize, OUT_SMEM);

    prep_kernel<<<112, 256>>>(Wv, Woff, Wattn, Wout);
    proj_kernel<<<NTOT / 128, 256, PROJ_SMEM>>>(query, bv, boff, battn);
    sample_kernel<<<NTOT / 4, 128>>>();
    out_kernel<<<NTOT / 128, 256, OUT_SMEM>>>(bout, query, out);
}